// round 10
// baseline (speedup 1.0000x reference)
#include <cuda_runtime.h>
#include <cuda_bf16.h>

#define NBATCH 8
#define SEQ 2048
#define DM 512
#define NH 8
#define DKV 64
#define ROWS (NBATCH*SEQ)              // 16384

#define HID_ELEMS (ROWS*DM)            // 8388608
#define PB_ELEMS (NH*SEQ*SEQ)          // 33554432
#define WELEMS (DM*DM)                 // 262144
#define LOG2E 1.4426950408889634f

// scratch (device globals: allocation-free per harness rules)
__device__ float g_bias[NH*4096];            // bias LUT (raw, for pb output)
__device__ float g_bias2[NH*4096];           // bias LUT * log2e (for attention)
__device__ __nv_bfloat16 g_ahi[HID_ELEMS];   // split activations (normed, then ctx)
__device__ __nv_bfloat16 g_alo[HID_ELEMS];
__device__ __nv_bfloat16 g_whi[4*WELEMS];    // wq|wk|wv|wo hi
__device__ __nv_bfloat16 g_wlo[4*WELEMS];
__device__ __nv_bfloat16 g_qkvh[3*HID_ELEMS]; // q|k|v hi (q pre-scaled by log2e)
__device__ __nv_bfloat16 g_qkvl[3*HID_ELEMS]; // lo

// ---------------------------------------------------------------------------
// helpers
// ---------------------------------------------------------------------------
__device__ __forceinline__ unsigned smem_u32(const void* p) {
    unsigned a;
    asm("{ .reg .u64 t; cvta.to.shared.u64 t, %1; cvt.u32.u64 %0, t; }" : "=r"(a) : "l"(p));
    return a;
}
__device__ __forceinline__ void ldsm4(unsigned* r, unsigned addr) {
    asm volatile("ldmatrix.sync.aligned.m8n8.x4.shared.b16 {%0,%1,%2,%3}, [%4];"
        : "=r"(r[0]), "=r"(r[1]), "=r"(r[2]), "=r"(r[3]) : "r"(addr));
}
__device__ __forceinline__ void ldsm4t(unsigned* r, unsigned addr) {
    asm volatile("ldmatrix.sync.aligned.m8n8.x4.trans.shared.b16 {%0,%1,%2,%3}, [%4];"
        : "=r"(r[0]), "=r"(r[1]), "=r"(r[2]), "=r"(r[3]) : "r"(addr));
}
__device__ __forceinline__ void mma16816(float* c, const unsigned* a, unsigned b0, unsigned b1) {
    asm volatile("mma.sync.aligned.m16n8k16.row.col.f32.bf16.bf16.f32 "
        "{%0,%1,%2,%3}, {%4,%5,%6,%7}, {%8,%9}, {%0,%1,%2,%3};"
        : "+f"(c[0]), "+f"(c[1]), "+f"(c[2]), "+f"(c[3])
        : "r"(a[0]), "r"(a[1]), "r"(a[2]), "r"(a[3]), "r"(b0), "r"(b1));
}
__device__ __forceinline__ void cp16(unsigned saddr, const void* g) {
    asm volatile("cp.async.ca.shared.global [%0], [%1], 16;" :: "r"(saddr), "l"(g));
}
#define CP_COMMIT() asm volatile("cp.async.commit_group;")
#define CP_WAIT(N)  asm volatile("cp.async.wait_group %0;" :: "n"(N))

__device__ __forceinline__ unsigned pack_bf16x2(float a, float b) {
    unsigned sa = __bfloat16_as_ushort(__float2bfloat16(a));
    unsigned sb = __bfloat16_as_ushort(__float2bfloat16(b));
    return sa | (sb << 16);
}
__device__ __forceinline__ void split2(float a, float b, unsigned& uh, unsigned& ul) {
    __nv_bfloat16 ha = __float2bfloat16(a), hb = __float2bfloat16(b);
    uh = (unsigned)__bfloat16_as_ushort(ha) | ((unsigned)__bfloat16_as_ushort(hb) << 16);
    ul = pack_bf16x2(a - __bfloat162float(ha), b - __bfloat162float(hb));
}
// exp2 via magic-constant range reduction + deg-5 Taylor; FMA/ALU pipes, no MUFU
__device__ __forceinline__ float exp2_poly(float y) {
    float t = y + 12582912.0f;                 // 1.5 * 2^23
    int k = __float_as_int(t);
    float f = y - (t - 12582912.0f);
    float p = 1.3333558146e-3f;
    p = fmaf(p, f, 9.6181291076e-3f);
    p = fmaf(p, f, 5.5504108664e-2f);
    p = fmaf(p, f, 2.4022650696e-1f);
    p = fmaf(p, f, 6.9314718056e-1f);
    p = fmaf(p, f, 1.0f);
    return __int_as_float(__float_as_int(p) + (k << 23));
}

// ---------------------------------------------------------------------------
// Relative-position bias LUTs (exact integer floor of T5 bucket formula)
// ---------------------------------------------------------------------------
__global__ void bias_fill_kernel(const float* __restrict__ table,
                                 float* __restrict__ out_remain) {
    int idx = blockIdx.x * blockDim.x + threadIdx.x;
    if (idx < NH * 4096) {
        int h = idx >> 12;
        int rel = (idx & 4095) - 2047;      // k - q
        int a = rel < 0 ? -rel : rel;
        int b;
        if (a < 8) {
            b = a;
        } else {
            int e = 28 - __clz(a);
            long long aa = (long long)a * (long long)a;
            int v = 2 * e + ((aa >= (1LL << (2 * e + 7))) ? 1 : 0);
            b = 8 + v;
            if (b > 15) b = 15;
        }
        int bucket = (rel > 0 ? 16 : 0) + b;
        float val = table[bucket * NH + h];
        g_bias[idx] = val;
        g_bias2[idx] = val * LOG2E;
    }
    if (out_remain != nullptr && idx < 8) out_remain[idx] = (float)idx;
}

__global__ void pb_write_kernel(float* __restrict__ out_pb) {
    int q = blockIdx.x, h = blockIdx.y;
    const float* brow = g_bias + h * 4096 + (2047 - q);
    float* dst = out_pb + ((size_t)(h * SEQ + q)) * SEQ;
    int t = threadIdx.x;
    #pragma unroll
    for (int it = 0; it < 2; it++) {
        int k4 = (t + it * 256) * 4;
        float4 v = make_float4(brow[k4], brow[k4+1], brow[k4+2], brow[k4+3]);
        *(float4*)&dst[k4] = v;
    }
}

// ---------------------------------------------------------------------------
// Weight split
// ---------------------------------------------------------------------------
__global__ void split_w_kernel(const float* __restrict__ wq, const float* __restrict__ wk,
                               const float* __restrict__ wv, const float* __restrict__ wo) {
    int idx = blockIdx.x * 256 + threadIdx.x;
    const float* src = (idx < WELEMS) ? wq : (idx < 2*WELEMS) ? wk : (idx < 3*WELEMS) ? wv : wo;
    float x = src[idx & (WELEMS - 1)];
    __nv_bfloat16 h = __float2bfloat16(x);
    g_whi[idx] = h;
    g_wlo[idx] = __float2bfloat16(x - __bfloat162float(h));
}

// ---------------------------------------------------------------------------
// Activation split with fused T5 RMS + ln weight
// ---------------------------------------------------------------------------
__global__ void split_a_kernel(const float* __restrict__ hidden, const float* __restrict__ lnw) {
    int m = blockIdx.x, t = threadIdx.x;
    float4 v = *(const float4*)&hidden[(size_t)m * DM + t * 4];
    float s = v.x*v.x + v.y*v.y + v.z*v.z + v.w*v.w;
    #pragma unroll
    for (int off = 16; off > 0; off >>= 1) s += __shfl_xor_sync(0xffffffffu, s, off);
    __shared__ float ws[4];
    if ((t & 31) == 0) ws[t >> 5] = s;
    __syncthreads();
    float rms = rsqrtf((ws[0]+ws[1]+ws[2]+ws[3]) * (1.0f/(float)DM) + 1e-6f);
    float4 l = *(const float4*)&lnw[t * 4];
    float a0 = v.x * l.x * rms, a1 = v.y * l.y * rms;
    float a2 = v.z * l.z * rms, a3 = v.w * l.w * rms;
    unsigned uh0, ul0, uh1, ul1;
    split2(a0, a1, uh0, ul0);
    split2(a2, a3, uh1, ul1);
    *(uint2*)&g_ahi[(size_t)m * DM + t * 4] = make_uint2(uh0, uh1);
    *(uint2*)&g_alo[(size_t)m * DM + t * 4] = make_uint2(ul0, ul1);
}

// ---------------------------------------------------------------------------
// bf16x3 tensor-core GEMM with 2-stage cp.async pipeline (same pattern as
// the attention kernel). CTA tile 128m x 64n, k-step 32.
// Dynamic smem: 2 stages x { Ahi,Alo [128][40] + Whi,Wlo [32][72] } bf16.
// ---------------------------------------------------------------------------
#define G_APITCH 40
#define G_WPITCH 72
#define G_A_PLANE (128*G_APITCH)               // 5120 elems
#define G_W_PLANE (32*G_WPITCH)                // 2304 elems
#define G_STAGE_B ((2*G_A_PLANE + 2*G_W_PLANE)*2)   // 29696 bytes
#define G_SMEM_B (2*G_STAGE_B)                 // 59392 bytes

__global__ __launch_bounds__(256) void mma_gemm_kernel(
    const __nv_bfloat16* __restrict__ Ahi, const __nv_bfloat16* __restrict__ Alo,
    const __nv_bfloat16* __restrict__ WhiB, const __nv_bfloat16* __restrict__ WloB,
    float* __restrict__ DstF,
    __nv_bfloat16* __restrict__ DstH, __nv_bfloat16* __restrict__ DstL,
    long long dst_z_stride, const float* __restrict__ resid, int qkv_mode)
{
    extern __shared__ char gs[];
    unsigned sbase = smem_u32(gs);

    int t = threadIdx.x, w = t >> 5, lane = t & 31;
    int n0 = blockIdx.x * 64, m0 = blockIdx.y * 128, z = blockIdx.z;
    const __nv_bfloat16* Wh = WhiB + (size_t)z * WELEMS;
    const __nv_bfloat16* Wl = WloB + (size_t)z * WELEMS;

    int wm = (w >> 1) * 32, wn = (w & 1) * 32;
    float c[2][4][4];
    #pragma unroll
    for (int i = 0; i < 2; i++)
        #pragma unroll
        for (int j = 0; j < 4; j++)
            #pragma unroll
            for (int k = 0; k < 4; k++) c[i][j][k] = 0.0f;

    int lrowA = lane & 15, lkA = (lane >> 4) * 8;
    int lkB = (lane & 7) + ((lane & 8) ? 8 : 0);
    int lnB = (lane & 16) ? 8 : 0;

    // prefetch of k-step k0_ into stage st
    #define GEMM_PREFETCH(k0_, st) do {                                          \
        unsigned sA_h = sbase + (unsigned)(st) * G_STAGE_B;                      \
        unsigned sA_l = sA_h + G_A_PLANE*2;                                      \
        unsigned sW_h = sA_l + G_A_PLANE*2;                                      \
        unsigned sW_l = sW_h + G_W_PLANE*2;                                      \
        _Pragma("unroll")                                                        \
        for (int it = 0; it < 2; it++) {                                         \
            int slot = t + 256*it;            /* 512 slots: 128 rows x 4 c8 */   \
            int row = slot >> 2, c8 = (slot & 3) * 8;                            \
            unsigned so = (unsigned)(row*G_APITCH + c8) * 2;                     \
            size_t go = (size_t)(m0 + row)*DM + (k0_) + c8;                      \
            cp16(sA_h + so, &Ahi[go]);                                           \
            cp16(sA_l + so, &Alo[go]);                                           \
        }                                                                        \
        {                                                                        \
            int row = t >> 3, c8 = (t & 7) * 8;   /* 256 slots: 32 x 8 */        \
            unsigned so = (unsigned)(row*G_WPITCH + c8) * 2;                     \
            size_t go = (size_t)((k0_) + row)*DM + n0 + c8;                      \
            cp16(sW_h + so, &Wh[go]);                                            \
            cp16(sW_l + so, &Wl[go]);                                            \
        }                                                                        \
        CP_COMMIT();                                                             \
    } while (0)

    GEMM_PREFETCH(0, 0);

    const int NK = DM / 32;   // 16
    for (int ks = 0; ks < NK; ks++) {
        int st = ks & 1;
        if (ks + 1 < NK) {
            GEMM_PREFETCH((ks + 1) * 32, st ^ 1);
            CP_WAIT(1);
        } else {
            CP_WAIT(0);
        }
        __syncthreads();

        unsigned aAh = sbase + (unsigned)st * G_STAGE_B;
        unsigned aAl = aAh + G_A_PLANE*2;
        unsigned aWh = aAl + G_A_PLANE*2;
        unsigned aWl = aWh + G_W_PLANE*2;

        #pragma unroll
        for (int kk = 0; kk < 32; kk += 16) {
            unsigned ah[2][4], al[2][4], bh[2][4], bl[2][4];
            #pragma unroll
            for (int mf = 0; mf < 2; mf++) {
                unsigned off = (unsigned)((wm + mf*16 + lrowA)*G_APITCH + kk + lkA) * 2;
                ldsm4(ah[mf], aAh + off);
                ldsm4(al[mf], aAl + off);
            }
            #pragma unroll
            for (int nh = 0; nh < 2; nh++) {
                unsigned off = (unsigned)((kk + lkB)*G_WPITCH + wn + nh*16 + lnB) * 2;
                ldsm4t(bh[nh], aWh + off);
                ldsm4t(bl[nh], aWl + off);
            }
            #pragma unroll
            for (int mf = 0; mf < 2; mf++)
                #pragma unroll
                for (int nf = 0; nf < 4; nf++) {
                    unsigned b0h = bh[nf >> 1][(nf & 1)*2], b1h = bh[nf >> 1][(nf & 1)*2 + 1];
                    unsigned b0l = bl[nf >> 1][(nf & 1)*2], b1l = bl[nf >> 1][(nf & 1)*2 + 1];
                    mma16816(c[mf][nf], ah[mf], b0h, b1h);
                    mma16816(c[mf][nf], ah[mf], b0l, b1l);
                    mma16816(c[mf][nf], al[mf], b0h, b1h);
                }
        }
        __syncthreads();   // stage st fully consumed before it is refilled
    }

    int g = lane >> 2, tc = (lane & 3) * 2;
    float sc = (qkv_mode && z == 0) ? LOG2E : 1.0f;
    #pragma unroll
    for (int mf = 0; mf < 2; mf++)
        #pragma unroll
        for (int nf = 0; nf < 4; nf++) {
            int row = m0 + wm + mf*16 + g;
            int col = n0 + wn + nf*8 + tc;
            float v0 = c[mf][nf][0] * sc, v1 = c[mf][nf][1] * sc;
            float v2 = c[mf][nf][2] * sc, v3 = c[mf][nf][3] * sc;
            if (DstF) {
                float* Dst = DstF;
                if (resid) {
                    float2 r0 = *(const float2*)&resid[(size_t)row*DM + col];
                    float2 r1 = *(const float2*)&resid[(size_t)(row+8)*DM + col];
                    v0 += r0.x; v1 += r0.y; v2 += r1.x; v3 += r1.y;
                }
                *(float2*)&Dst[(size_t)row*DM + col] = make_float2(v0, v1);
                *(float2*)&Dst[(size_t)(row+8)*DM + col] = make_float2(v2, v3);
            } else {
                size_t zo = (size_t)z * dst_z_stride;
                unsigned uh, ul;
                split2(v0, v1, uh, ul);
                *(unsigned*)&DstH[zo + (size_t)row*DM + col] = uh;
                *(unsigned*)&DstL[zo + (size_t)row*DM + col] = ul;
                split2(v2, v3, uh, ul);
                *(unsigned*)&DstH[zo + (size_t)(row+8)*DM + col] = uh;
                *(unsigned*)&DstL[zo + (size_t)(row+8)*DM + col] = ul;
            }
        }
}

// ---------------------------------------------------------------------------
// Tensor-core flash attention v2 (unchanged from round 8 — known good):
//   - 128 q-rows per CTA (256 threads, 8 warps; warp w owns rows 16w..16w+15)
//   - 2-stage cp.async pipeline on K/V (double-buffered dynamic smem)
//   - no online max (scores bounded; 2^y safe in fp32), exp2 on FMA pipe
// ---------------------------------------------------------------------------
#define ATT_PLANE (64*72)                    // bf16 elems per plane
#define ATT_STAGE_B (4*ATT_PLANE*2)          // 36864 bytes per stage
#define ATT_SMEM_B (2*ATT_STAGE_B + 2*192*4) // 75264 bytes

__global__ __launch_bounds__(256) void attn_mma_kernel(
    const __nv_bfloat16* __restrict__ Qh, const __nv_bfloat16* __restrict__ Ql,
    const __nv_bfloat16* __restrict__ Kh, const __nv_bfloat16* __restrict__ Kl,
    const __nv_bfloat16* __restrict__ Vh, const __nv_bfloat16* __restrict__ Vl,
    __nv_bfloat16* __restrict__ Chi, __nv_bfloat16* __restrict__ Clo,
    const float* __restrict__ Bias2)
{
    extern __shared__ char dyns[];
    __nv_bfloat16* sKV = (__nv_bfloat16*)dyns;         // 2 stages
    float* sB = (float*)(dyns + 2*ATT_STAGE_B);        // [2][192]

    int t = threadIdx.x, w = t >> 5, lane = t & 31;
    int g = lane >> 2, cq = lane & 3;
    int q0 = blockIdx.x * 128, h = blockIdx.y, n = blockIdx.z;
    size_t base = ((size_t)n * SEQ) * DM + h * DKV;
    const float* brow = Bias2 + h * 4096;

    unsigned sbase = smem_u32(dyns);

    // ---- Q prologue: stage [128][72] hi/lo into stage area, ldmatrix frags ----
    {
        __nv_bfloat16* Qs_h = sKV;
        __nv_bfloat16* Qs_l = sKV + 128*72;
        #pragma unroll
        for (int it = 0; it < 4; it++) {
            int slot = t + 256*it;
            int row = slot >> 3, c8 = (slot & 7) * 8;
            *(uint4*)&Qs_h[row*72 + c8] = *(const uint4*)&Qh[base + (size_t)(q0+row)*DM + c8];
            *(uint4*)&Qs_l[row*72 + c8] = *(const uint4*)&Ql[base + (size_t)(q0+row)*DM + c8];
        }
    }
    __syncthreads();
    unsigned qfh[4][4], qfl[4][4];
    unsigned aQh = sbase, aQl = sbase + 128*72*2;
    #pragma unroll
    for (int kk = 0; kk < 4; kk++) {
        unsigned addr = (unsigned)((16*w + (lane & 15))*72 + 16*kk + ((lane >> 4)*8)) * 2;
        ldsm4(qfh[kk], aQh + addr);
        ldsm4(qfl[kk], aQl + addr);
    }
    __syncthreads();

    float O[8][4];
    #pragma unroll
    for (int j = 0; j < 8; j++)
        #pragma unroll
        for (int e = 0; e < 4; e++) O[j][e] = 0.0f;
    float lac0 = 0.0f, lac1 = 0.0f;

    const int NB = SEQ / 64;

    #define ATT_PREFETCH(kb, st) do {                                            \
        int k0_ = (kb) * 64;                                                     \
        unsigned sst = sbase + (unsigned)(st) * ATT_STAGE_B;                     \
        _Pragma("unroll")                                                        \
        for (int it = 0; it < 2; it++) {                                         \
            int slot = t + 256*it;                                               \
            int row = slot >> 3, c8 = (slot & 7) * 8;                            \
            unsigned so = (unsigned)(row*72 + c8) * 2;                           \
            size_t go = base + (size_t)(k0_ + row)*DM + c8;                      \
            cp16(sst + so,                    &Kh[go]);                          \
            cp16(sst + ATT_PLANE*2   + so,    &Kl[go]);                          \
            cp16(sst + ATT_PLANE*4   + so,    &Vh[go]);                          \
            cp16(sst + ATT_PLANE*6   + so,    &Vl[go]);                          \
        }                                                                        \
        if (t < 192) sB[(st)*192 + t] = brow[k0_ - q0 + 1920 + t];               \
        CP_COMMIT();                                                             \
    } while (0)

    ATT_PREFETCH(0, 0);

    for (int kb = 0; kb < NB; kb++) {
        int st = kb & 1;
        if (kb + 1 < NB) {
            ATT_PREFETCH(kb + 1, st ^ 1);
            CP_WAIT(1);
        } else {
            CP_WAIT(0);
        }
        __syncthreads();

        unsigned aKh = sbase + (unsigned)st * ATT_STAGE_B;
        unsigned aKl = aKh + ATT_PLANE*2;
        unsigned aVh = aKh + ATT_PLANE*4;
        unsigned aVl = aKh + ATT_PLANE*6;
        const float* sBc = sB + st*192;

        // ---- S = Q K^T (bf16x3) ----
        float S[8][4];
        #pragma unroll
        for (int j = 0; j < 8; j++)
            #pragma unroll
            for (int e = 0; e < 4; e++) S[j][e] = 0.0f;

        #pragma unroll
        for (int kk = 0; kk < 4; kk++) {
            #pragma unroll
            for (int u = 0; u < 4; u++) {
                unsigned bh[4], bl[4];
                unsigned addr = (unsigned)((16*u + (lane & 7) + ((lane & 16) ? 8 : 0))*72
                                           + 16*kk + ((lane & 8) ? 8 : 0)) * 2;
                ldsm4(bh, aKh + addr);
                ldsm4(bl, aKl + addr);
                #pragma unroll
                for (int jj = 0; jj < 2; jj++) {
                    int j = 2*u + jj;
                    mma16816(S[j], qfh[kk], bh[2*jj], bh[2*jj+1]);
                    mma16816(S[j], qfl[kk], bh[2*jj], bh[2*jj+1]);
                    mma16816(S[j], qfh[kk], bl[2*jj], bl[2*jj+1]);
                }
            }
        }

        // ---- bias + exp2 + split to P frags ----
        unsigned aPh[4][4], aPl[4][4];
        int r0 = 16*w + g;
        #pragma unroll
        for (int j = 0; j < 8; j++) {
            int col = 8*j + 2*cq;
            float p0 = exp2_poly(S[j][0] + sBc[col     - r0 + 127]);
            float p1 = exp2_poly(S[j][1] + sBc[col + 1 - r0 + 127]);
            float p2 = exp2_poly(S[j][2] + sBc[col     - r0 + 119]);
            float p3 = exp2_poly(S[j][3] + sBc[col + 1 - r0 + 119]);
            lac0 += p0 + p1;
            lac1 += p2 + p3;
            unsigned uh01, ul01, uh23, ul23;
            split2(p0, p1, uh01, ul01);
            split2(p2, p3, uh23, ul23);
            aPh[j >> 1][(j & 1)*2    ] = uh01;
            aPh[j >> 1][(j & 1)*2 + 1] = uh23;
            aPl[j >> 1][(j & 1)*2    ] = ul01;
            aPl[j >> 1][(j & 1)*2 + 1] = ul23;
        }

        // ---- O += P V (bf16x3) ----
        #pragma unroll
        for (int kkk = 0; kkk < 4; kkk++) {
            #pragma unroll
            for (int u2 = 0; u2 < 4; u2++) {
                unsigned bh[4], bl[4];
                unsigned addr = (unsigned)((16*kkk + (lane & 7) + ((lane & 8) ? 8 : 0))*72
                                           + 16*u2 + ((lane & 16) ? 8 : 0)) * 2;
                ldsm4t(bh, aVh + addr);
                ldsm4t(bl, aVl + addr);
                #pragma unroll
                for (int jj = 0; jj < 2; jj++) {
                    int j = 2*u2 + jj;
                    mma16816(O[j], aPh[kkk], bh[2*jj], bh[2*jj+1]);
                    mma16816(O[j], aPl[kkk], bh[2*jj], bh[2*jj+1]);
                    mma16816(O[j], aPh[kkk], bl[2*jj], bl[2*jj+1]);
                }
            }
        }
        __syncthreads();
    }

    // normalize and write ctx (bf16 hi/lo)
    lac0 += __shfl_xor_sync(0xffffffffu, lac0, 1);
    lac0 += __shfl_xor_sync(0xffffffffu, lac0, 2);
    lac1 += __shfl_xor_sync(0xffffffffu, lac1, 1);
    lac1 += __shfl_xor_sync(0xffffffffu, lac1, 2);
    float li0 = 1.0f / lac0, li1 = 1.0f / lac1;

    size_t rowA = base + (size_t)(q0 + 16*w + g) * DM;
    size_t rowB = base + (size_t)(q0 + 16*w + g + 8) * DM;
    #pragma unroll
    for (int j = 0; j < 8; j++) {
        int col = 8*j + 2*cq;
        unsigned uh, ul;
        split2(O[j][0] * li0, O[j][1] * li0, uh, ul);
        *(unsigned*)&Chi[rowA + col] = uh;
        *(unsigned*)&Clo[rowA + col] = ul;
        split2(O[j][2] * li1, O[j][3] * li1, uh, ul);
        *(unsigned*)&Chi[rowB + col] = uh;
        *(unsigned*)&Clo[rowB + col] = ul;
    }
}

// ---------------------------------------------------------------------------
extern "C" void kernel_launch(void* const* d_in, const int* in_sizes, int n_in,
                              void* d_out, int out_size) {
    const float* hidden = (const float*)d_in[0];
    const float* lnw    = (const float*)d_in[1];
    const float* wq     = (const float*)d_in[2];
    const float* wk     = (const float*)d_in[3];
    const float* wv     = (const float*)d_in[4];
    const float* wo     = (const float*)d_in[5];
    const float* table  = (const float*)d_in[6];
    float* out = (float*)d_out;

    // real device addresses of __device__ symbols (NOT host shadows)
    float *pbias2;
    __nv_bfloat16 *pahi, *palo, *pwhi, *pwlo, *pqh, *pql;
    cudaGetSymbolAddress((void**)&pbias2, g_bias2);
    cudaGetSymbolAddress((void**)&pahi,   g_ahi);
    cudaGetSymbolAddress((void**)&palo,   g_alo);
    cudaGetSymbolAddress((void**)&pwhi,   g_whi);
    cudaGetSymbolAddress((void**)&pwlo,   g_wlo);
    cudaGetSymbolAddress((void**)&pqh,    g_qkvh);
    cudaGetSymbolAddress((void**)&pql,    g_qkvl);

    cudaFuncSetAttribute(attn_mma_kernel,
                         cudaFuncAttributeMaxDynamicSharedMemorySize, ATT_SMEM_B);
    cudaFuncSetAttribute(mma_gemm_kernel,
                         cudaFuncAttributeMaxDynamicSharedMemorySize, G_SMEM_B);

    bool full = out_size >= (HID_ELEMS + PB_ELEMS + 8);
    float* out_pb     = out + HID_ELEMS;
    float* out_remain = out + HID_ELEMS + PB_ELEMS;

    bias_fill_kernel<<<128, 256>>>(table, full ? out_remain : nullptr);
    if (full) pb_write_kernel<<<dim3(SEQ, NH), 256>>>(out_pb);

    split_w_kernel<<<4*WELEMS/256, 256>>>(wq, wk, wv, wo);
    split_a_kernel<<<ROWS, 128>>>(hidden, lnw);

    // QKV projections -> bf16 hi/lo planes (Q scaled by log2e)
    mma_gemm_kernel<<<dim3(DM/64, ROWS/128, 3), 256, G_SMEM_B>>>(
        pahi, palo, pwhi, pwlo, nullptr, pqh, pql,
        (long long)HID_ELEMS, nullptr, 1);

    // attention: ctx -> g_ahi/g_alo (bf16 hi/lo)
    attn_mma_kernel<<<dim3(SEQ/128, NH, NBATCH), 256, ATT_SMEM_B>>>(
        pqh,                pql,
        pqh +   HID_ELEMS,  pql +   HID_ELEMS,
        pqh + 2*HID_ELEMS,  pql + 2*HID_ELEMS,
        pahi, palo, pbias2);

    // output projection + residual (fp32 out)
    mma_gemm_kernel<<<dim3(DM/64, ROWS/128, 1), 256, G_SMEM_B>>>(
        pahi, palo, pwhi + 3*WELEMS, pwlo + 3*WELEMS, out,
        nullptr, nullptr, 0, hidden, 0);
}

// round 12
// speedup vs baseline: 1.0623x; 1.0623x over previous
#include <cuda_runtime.h>
#include <cuda.h>
#include <cuda_bf16.h>

#define NBATCH 8
#define SEQ 2048
#define DM 512
#define NH 8
#define DKV 64
#define ROWS (NBATCH*SEQ)
#define HID_ELEMS (ROWS*DM)
#define PB_ELEMS (NH*SEQ*SEQ)
#define WELEMS (DM*DM)
#define LOG2E 1.4426950408889634f

__device__ float g_bias[NH*4096];
__device__ float g_bias2[NH*4096];
__device__ __nv_bfloat16 g_ahi[HID_ELEMS];
__device__ __nv_bfloat16 g_alo[HID_ELEMS];
__device__ __nv_bfloat16 g_whi[4*WELEMS];    // [z][k][n]
__device__ __nv_bfloat16 g_wlo[4*WELEMS];
__device__ __nv_bfloat16 g_qkvh[3*HID_ELEMS];
__device__ __nv_bfloat16 g_qkvl[3*HID_ELEMS];

// ---------------- helpers ----------------
__device__ __forceinline__ unsigned smem_u32(const void* p) {
    unsigned a;
    asm("{ .reg .u64 t; cvta.to.shared.u64 t, %1; cvt.u32.u64 %0, t; }" : "=r"(a) : "l"(p));
    return a;
}
__device__ __forceinline__ unsigned sw128(unsigned x) { return x ^ ((x >> 3) & 0x70u); }
__device__ __forceinline__ void ldsm4(unsigned* r, unsigned addr) {
    asm volatile("ldmatrix.sync.aligned.m8n8.x4.shared.b16 {%0,%1,%2,%3}, [%4];"
        : "=r"(r[0]), "=r"(r[1]), "=r"(r[2]), "=r"(r[3]) : "r"(addr));
}
__device__ __forceinline__ void ldsm4t(unsigned* r, unsigned addr) {
    asm volatile("ldmatrix.sync.aligned.m8n8.x4.trans.shared.b16 {%0,%1,%2,%3}, [%4];"
        : "=r"(r[0]), "=r"(r[1]), "=r"(r[2]), "=r"(r[3]) : "r"(addr));
}
__device__ __forceinline__ void mma16816(float* c, const unsigned* a, unsigned b0, unsigned b1) {
    asm volatile("mma.sync.aligned.m16n8k16.row.col.f32.bf16.bf16.f32 "
        "{%0,%1,%2,%3}, {%4,%5,%6,%7}, {%8,%9}, {%0,%1,%2,%3};"
        : "+f"(c[0]), "+f"(c[1]), "+f"(c[2]), "+f"(c[3])
        : "r"(a[0]), "r"(a[1]), "r"(a[2]), "r"(a[3]), "r"(b0), "r"(b1));
}
__device__ __forceinline__ void tma2(unsigned dst, const CUtensorMap* m, int x, int y, unsigned mbar) {
    asm volatile("cp.async.bulk.tensor.2d.shared::cta.global.tile.mbarrier::complete_tx::bytes "
        "[%0], [%1, {%2, %3}], [%4];" :: "r"(dst), "l"(m), "r"(x), "r"(y), "r"(mbar) : "memory");
}
#define MBAR_INIT(a,c)   asm volatile("mbarrier.init.shared.b64 [%0], %1;" :: "r"((unsigned)(a)), "r"((unsigned)(c)) : "memory")
#define MBAR_EXPECT(a,b) asm volatile("mbarrier.arrive.expect_tx.shared.b64 _, [%0], %1;" :: "r"((unsigned)(a)), "r"((unsigned)(b)) : "memory")
__device__ __forceinline__ void mbar_wait(unsigned a, unsigned p) {
    asm volatile("{\n\t.reg .pred P;\n\tWL%=:\n\t"
        "mbarrier.try_wait.parity.acquire.cta.shared::cta.b64 P, [%0], %1, 0x989680;\n\t"
        "@P bra.uni WD%=;\n\tbra.uni WL%=;\n\tWD%=:\n\t}" :: "r"(a), "r"(p) : "memory");
}
__device__ __forceinline__ unsigned pack_bf16x2(float a, float b) {
    unsigned sa = __bfloat16_as_ushort(__float2bfloat16(a));
    unsigned sb = __bfloat16_as_ushort(__float2bfloat16(b));
    return sa | (sb << 16);
}
__device__ __forceinline__ void split2(float a, float b, unsigned& uh, unsigned& ul) {
    __nv_bfloat16 ha = __float2bfloat16(a), hb = __float2bfloat16(b);
    uh = (unsigned)__bfloat16_as_ushort(ha) | ((unsigned)__bfloat16_as_ushort(hb) << 16);
    ul = pack_bf16x2(a - __bfloat162float(ha), b - __bfloat162float(hb));
}
__device__ __forceinline__ float exp2_poly(float y) {
    float t = y + 12582912.0f;
    int k = __float_as_int(t);
    float f = y - (t - 12582912.0f);
    float p = 1.3333558146e-3f;
    p = fmaf(p, f, 9.6181291076e-3f);
    p = fmaf(p, f, 5.5504108664e-2f);
    p = fmaf(p, f, 2.4022650696e-1f);
    p = fmaf(p, f, 6.9314718056e-1f);
    p = fmaf(p, f, 1.0f);
    return __int_as_float(__float_as_int(p) + (k << 23));
}

// ---------------- small kernels ----------------
__global__ void bias_fill_kernel(const float* __restrict__ table, float* __restrict__ out_remain) {
    int idx = blockIdx.x * blockDim.x + threadIdx.x;
    if (idx < NH * 4096) {
        int h = idx >> 12;
        int rel = (idx & 4095) - 2047;
        int a = rel < 0 ? -rel : rel;
        int b;
        if (a < 8) b = a;
        else {
            int e = 28 - __clz(a);
            long long aa = (long long)a * (long long)a;
            b = 8 + 2*e + ((aa >= (1LL << (2*e + 7))) ? 1 : 0);
            if (b > 15) b = 15;
        }
        int bucket = (rel > 0 ? 16 : 0) + b;
        float val = table[bucket * NH + h];
        g_bias[idx] = val;
        g_bias2[idx] = val * LOG2E;
    }
    if (out_remain != nullptr && idx < 8) out_remain[idx] = (float)idx;
}

__global__ void pb_write_kernel(float* __restrict__ out_pb) {
    int q = blockIdx.x, h = blockIdx.y;
    const float* brow = g_bias + h * 4096 + (2047 - q);
    float* dst = out_pb + ((size_t)(h * SEQ + q)) * SEQ;
    int t = threadIdx.x;
    #pragma unroll
    for (int it = 0; it < 2; it++) {
        int k4 = (t + it * 256) * 4;
        *(float4*)&dst[k4] = make_float4(brow[k4], brow[k4+1], brow[k4+2], brow[k4+3]);
    }
}

__global__ void split_w_kernel(const float* __restrict__ wq, const float* __restrict__ wk,
                               const float* __restrict__ wv, const float* __restrict__ wo) {
    int idx = blockIdx.x * 256 + threadIdx.x;
    const float* src = (idx < WELEMS) ? wq : (idx < 2*WELEMS) ? wk : (idx < 3*WELEMS) ? wv : wo;
    float x = src[idx & (WELEMS - 1)];
    __nv_bfloat16 h = __float2bfloat16(x);
    g_whi[idx] = h;
    g_wlo[idx] = __float2bfloat16(x - __bfloat162float(h));
}

__global__ void split_a_kernel(const float* __restrict__ hidden, const float* __restrict__ lnw) {
    int m = blockIdx.x, t = threadIdx.x;
    float4 v = *(const float4*)&hidden[(size_t)m * DM + t * 4];
    float s = v.x*v.x + v.y*v.y + v.z*v.z + v.w*v.w;
    #pragma unroll
    for (int off = 16; off > 0; off >>= 1) s += __shfl_xor_sync(0xffffffffu, s, off);
    __shared__ float ws[4];
    if ((t & 31) == 0) ws[t >> 5] = s;
    __syncthreads();
    float rms = rsqrtf((ws[0]+ws[1]+ws[2]+ws[3]) * (1.0f/(float)DM) + 1e-6f);
    float4 l = *(const float4*)&lnw[t * 4];
    float a0 = v.x*l.x*rms, a1 = v.y*l.y*rms, a2 = v.z*l.z*rms, a3 = v.w*l.w*rms;
    unsigned uh0, ul0, uh1, ul1;
    split2(a0, a1, uh0, ul0);
    split2(a2, a3, uh1, ul1);
    *(uint2*)&g_ahi[(size_t)m * DM + t * 4] = make_uint2(uh0, uh1);
    *(uint2*)&g_alo[(size_t)m * DM + t * 4] = make_uint2(ul0, ul1);
}

// ---------------------------------------------------------------------------
// bf16x3 mma.sync GEMM, TMA-fed 2-stage pipeline. CTA 128m x 64n, k-step 64.
// Stage: Ah,Al [128][64] SW128 (16KB ea) + Wh,Wl [64][64] SW128 (8KB ea).
// ---------------------------------------------------------------------------
#define G_STG 49152u
#define G_DSM (2*49152 + 1024)

__global__ __launch_bounds__(256) void mma_gemm_kernel(
    const __grid_constant__ CUtensorMap mAh, const __grid_constant__ CUtensorMap mAl,
    const __grid_constant__ CUtensorMap mWh, const __grid_constant__ CUtensorMap mWl,
    int wbase, float* __restrict__ DstF,
    __nv_bfloat16* __restrict__ DstH, __nv_bfloat16* __restrict__ DstL,
    long long dzs, const float* __restrict__ resid, int qkv_mode)
{
    extern __shared__ char gsm[];
    __shared__ __align__(8) unsigned long long mb[2];
    unsigned sb = (smem_u32(gsm) + 1023u) & ~1023u;
    int t = threadIdx.x, w = t >> 5, lane = t & 31;
    int n0 = blockIdx.x * 64, m0 = blockIdx.y * 128, z = blockIdx.z;
    int wm = (w >> 1) * 32, wn = (w & 1) * 32;
    int wr = (wbase + z) * DM;

    float c[2][4][4];
    #pragma unroll
    for (int i = 0; i < 2; i++)
        #pragma unroll
        for (int j = 0; j < 4; j++)
            #pragma unroll
            for (int k = 0; k < 4; k++) c[i][j][k] = 0.0f;

    int lrowA = lane & 15, lkA = (lane >> 4) * 8;
    int lkB = (lane & 7) + ((lane & 8) ? 8 : 0);
    int lnB = (lane & 16) ? 8 : 0;

    if (t == 0) { MBAR_INIT(smem_u32(&mb[0]), 1); MBAR_INIT(smem_u32(&mb[1]), 1); }
    __syncthreads();
    if (t == 0) {
        unsigned m0b = smem_u32(&mb[0]);
        MBAR_EXPECT(m0b, G_STG);
        tma2(sb,         &mAh, 0, m0, m0b);
        tma2(sb + 16384, &mAl, 0, m0, m0b);
        tma2(sb + 32768, &mWh, n0, wr, m0b);
        tma2(sb + 40960, &mWl, n0, wr, m0b);
    }
    int ph[2] = {0, 0};
    for (int s = 0; s < 8; s++) {
        int b = s & 1;
        unsigned st = sb + (unsigned)b * G_STG;
        if (s + 1 < 8 && t == 0) {
            unsigned sn = sb + (unsigned)(b ^ 1) * G_STG;
            unsigned mbn = smem_u32(&mb[b ^ 1]);
            MBAR_EXPECT(mbn, G_STG);
            tma2(sn,         &mAh, (s+1)*64, m0, mbn);
            tma2(sn + 16384, &mAl, (s+1)*64, m0, mbn);
            tma2(sn + 32768, &mWh, n0, wr + (s+1)*64, mbn);
            tma2(sn + 40960, &mWl, n0, wr + (s+1)*64, mbn);
        }
        mbar_wait(smem_u32(&mb[b]), ph[b]); ph[b] ^= 1;

        #pragma unroll
        for (int kk = 0; kk < 64; kk += 16) {
            unsigned ah[2][4], al[2][4], bh[2][4], bl[2][4];
            #pragma unroll
            for (int mf = 0; mf < 2; mf++) {
                unsigned sa = sw128((unsigned)((wm + mf*16 + lrowA)*128 + (kk + lkA)*2));
                ldsm4(ah[mf], st + sa);
                ldsm4(al[mf], st + 16384 + sa);
            }
            #pragma unroll
            for (int nh = 0; nh < 2; nh++) {
                unsigned sa = sw128((unsigned)((kk + lkB)*128 + (wn + nh*16 + lnB)*2));
                ldsm4t(bh[nh], st + 32768 + sa);
                ldsm4t(bl[nh], st + 40960 + sa);
            }
            #pragma unroll
            for (int mf = 0; mf < 2; mf++)
                #pragma unroll
                for (int nf = 0; nf < 4; nf++) {
                    unsigned b0h = bh[nf >> 1][(nf & 1)*2], b1h = bh[nf >> 1][(nf & 1)*2 + 1];
                    unsigned b0l = bl[nf >> 1][(nf & 1)*2], b1l = bl[nf >> 1][(nf & 1)*2 + 1];
                    mma16816(c[mf][nf], ah[mf], b0h, b1h);
                    mma16816(c[mf][nf], ah[mf], b0l, b1l);
                    mma16816(c[mf][nf], al[mf], b0h, b1h);
                }
        }
        __syncthreads();   // stage b fully consumed before TMA refills it
    }

    int g = lane >> 2, tc = (lane & 3) * 2;
    float sc = (qkv_mode && z == 0) ? LOG2E : 1.0f;
    #pragma unroll
    for (int mf = 0; mf < 2; mf++)
        #pragma unroll
        for (int nf = 0; nf < 4; nf++) {
            int row = m0 + wm + mf*16 + g;
            int col = n0 + wn + nf*8 + tc;
            float v0 = c[mf][nf][0]*sc, v1 = c[mf][nf][1]*sc;
            float v2 = c[mf][nf][2]*sc, v3 = c[mf][nf][3]*sc;
            if (DstF) {
                if (resid) {
                    float2 r0 = *(const float2*)&resid[(size_t)row*DM + col];
                    float2 r1 = *(const float2*)&resid[(size_t)(row+8)*DM + col];
                    v0 += r0.x; v1 += r0.y; v2 += r1.x; v3 += r1.y;
                }
                *(float2*)&DstF[(size_t)row*DM + col] = make_float2(v0, v1);
                *(float2*)&DstF[(size_t)(row+8)*DM + col] = make_float2(v2, v3);
            } else {
                size_t zo = (size_t)z * dzs;
                unsigned uh, ul;
                split2(v0, v1, uh, ul);
                *(unsigned*)&DstH[zo + (size_t)row*DM + col] = uh;
                *(unsigned*)&DstL[zo + (size_t)row*DM + col] = ul;
                split2(v2, v3, uh, ul);
                *(unsigned*)&DstH[zo + (size_t)(row+8)*DM + col] = uh;
                *(unsigned*)&DstL[zo + (size_t)(row+8)*DM + col] = ul;
            }
        }
}

// ---------------------------------------------------------------------------
// Flash attention, TMA-fed K/V 2-stage pipeline (compute identical to round 8).
// Stage: Kh,Kl,Vh,Vl [64 seq][64 d] SW128 = 8KB each -> 32KB/stage.
// ---------------------------------------------------------------------------
#define ATT_STG 32768u
#define ATT_DSM (65536 + 1536 + 1024)

__global__ __launch_bounds__(256) void attn_mma_kernel(
    const __grid_constant__ CUtensorMap mH, const __grid_constant__ CUtensorMap mL,
    const __nv_bfloat16* __restrict__ Qh, const __nv_bfloat16* __restrict__ Ql,
    __nv_bfloat16* __restrict__ Chi, __nv_bfloat16* __restrict__ Clo,
    const float* __restrict__ Bias2)
{
    extern __shared__ char dyns[];
    __shared__ __align__(8) unsigned long long mb[2];
    unsigned sb = (smem_u32(dyns) + 1023u) & ~1023u;
    char* ab = dyns + (sb - smem_u32(dyns));
    float* sB = (float*)(ab + 65536);

    int t = threadIdx.x, w = t >> 5, lane = t & 31;
    int g = lane >> 2, cq = lane & 3;
    int q0 = blockIdx.x * 128, h = blockIdx.y, n = blockIdx.z;
    size_t base = ((size_t)n * SEQ) * DM + h * DKV;
    const float* brow = Bias2 + h * 4096;

    if (t == 0) { MBAR_INIT(smem_u32(&mb[0]), 1); MBAR_INIT(smem_u32(&mb[1]), 1); }

    // Q prologue: stage into scratch (overlaps stage area; used before prefetch 0)
    {
        __nv_bfloat16* Qs_h = (__nv_bfloat16*)ab;
        __nv_bfloat16* Qs_l = (__nv_bfloat16*)(ab + 18432);
        #pragma unroll
        for (int it = 0; it < 4; it++) {
            int slot = t + 256*it;
            int row = slot >> 3, c8 = (slot & 7) * 8;
            *(uint4*)&Qs_h[row*72 + c8] = *(const uint4*)&Qh[base + (size_t)(q0+row)*DM + c8];
            *(uint4*)&Qs_l[row*72 + c8] = *(const uint4*)&Ql[base + (size_t)(q0+row)*DM + c8];
        }
    }
    __syncthreads();
    unsigned qfh[4][4], qfl[4][4];
    #pragma unroll
    for (int kk = 0; kk < 4; kk++) {
        unsigned addr = (unsigned)((16*w + (lane & 15))*72 + 16*kk + ((lane >> 4)*8)) * 2;
        ldsm4(qfh[kk], sb + addr);
        ldsm4(qfl[kk], sb + 18432 + addr);
    }
    __syncthreads();   // Q reads done; mbarrier init visible; stage area free

    float O[8][4];
    #pragma unroll
    for (int j = 0; j < 8; j++)
        #pragma unroll
        for (int e = 0; e < 4; e++) O[j][e] = 0.0f;
    float lac0 = 0.0f, lac1 = 0.0f;

    int yK = ROWS + n*SEQ;   // K plane row base; V = +ROWS
    if (t == 0) {
        unsigned m0b = smem_u32(&mb[0]);
        MBAR_EXPECT(m0b, ATT_STG);
        tma2(sb,         &mH, h*64, yK, m0b);
        tma2(sb + 8192,  &mL, h*64, yK, m0b);
        tma2(sb + 16384, &mH, h*64, yK + ROWS, m0b);
        tma2(sb + 24576, &mL, h*64, yK + ROWS, m0b);
    }
    if (t < 192) sB[t] = brow[0 - q0 + 1920 + t];

    int ph[2] = {0, 0};
    const int NB = SEQ / 64;
    for (int kb = 0; kb < NB; kb++) {
        int st = kb & 1;
        unsigned stc = sb + (unsigned)st * ATT_STG;
        if (kb + 1 < NB) {
            if (t == 0) {
                unsigned stn = sb + (unsigned)(st ^ 1) * ATT_STG;
                unsigned mbn = smem_u32(&mb[st ^ 1]);
                MBAR_EXPECT(mbn, ATT_STG);
                int y = yK + (kb+1)*64;
                tma2(stn,         &mH, h*64, y, mbn);
                tma2(stn + 8192,  &mL, h*64, y, mbn);
                tma2(stn + 16384, &mH, h*64, y + ROWS, mbn);
                tma2(stn + 24576, &mL, h*64, y + ROWS, mbn);
            }
            if (t < 192) sB[(st^1)*192 + t] = brow[(kb+1)*64 - q0 + 1920 + t];
        }
        mbar_wait(smem_u32(&mb[st]), ph[st]); ph[st] ^= 1;
        __syncthreads();   // orders plain sB writes for this stage
        const float* sBc = sB + st*192;

        // ---- S = Q K^T (bf16x3) ----
        float S[8][4];
        #pragma unroll
        for (int j = 0; j < 8; j++)
            #pragma unroll
            for (int e = 0; e < 4; e++) S[j][e] = 0.0f;

        #pragma unroll
        for (int kk = 0; kk < 4; kk++) {
            #pragma unroll
            for (int u = 0; u < 4; u++) {
                unsigned bh[4], bl[4];
                unsigned sa = sw128((unsigned)((16*u + (lane & 7) + ((lane & 16) ? 8 : 0))*128
                                               + 32*kk + ((lane & 8) ? 16 : 0)));
                ldsm4(bh, stc + sa);
                ldsm4(bl, stc + 8192 + sa);
                #pragma unroll
                for (int jj = 0; jj < 2; jj++) {
                    int j = 2*u + jj;
                    mma16816(S[j], qfh[kk], bh[2*jj], bh[2*jj+1]);
                    mma16816(S[j], qfl[kk], bh[2*jj], bh[2*jj+1]);
                    mma16816(S[j], qfh[kk], bl[2*jj], bl[2*jj+1]);
                }
            }
        }

        // ---- bias + exp2 + split to P frags ----
        unsigned aPh[4][4], aPl[4][4];
        int r0 = 16*w + g;
        #pragma unroll
        for (int j = 0; j < 8; j++) {
            int col = 8*j + 2*cq;
            float p0 = exp2_poly(S[j][0] + sBc[col     - r0 + 127]);
            float p1 = exp2_poly(S[j][1] + sBc[col + 1 - r0 + 127]);
            float p2 = exp2_poly(S[j][2] + sBc[col     - r0 + 119]);
            float p3 = exp2_poly(S[j][3] + sBc[col + 1 - r0 + 119]);
            lac0 += p0 + p1;
            lac1 += p2 + p3;
            unsigned uh01, ul01, uh23, ul23;
            split2(p0, p1, uh01, ul01);
            split2(p2, p3, uh23, ul23);
            aPh[j >> 1][(j & 1)*2    ] = uh01;
            aPh[j >> 1][(j & 1)*2 + 1] = uh23;
            aPl[j >> 1][(j & 1)*2    ] = ul01;
            aPl[j >> 1][(j & 1)*2 + 1] = ul23;
        }

        // ---- O += P V (bf16x3) ----
        #pragma unroll
        for (int kkk = 0; kkk < 4; kkk++) {
            #pragma unroll
            for (int u2 = 0; u2 < 4; u2++) {
                unsigned bh[4], bl[4];
                unsigned sa = sw128((unsigned)((16*kkk + (lane & 7) + ((lane & 8) ? 8 : 0))*128
                                               + 32*u2 + ((lane & 16) ? 16 : 0)));
                ldsm4t(bh, stc + 16384 + sa);
                ldsm4t(bl, stc + 24576 + sa);
                #pragma unroll
                for (int jj = 0; jj < 2; jj++) {
                    int j = 2*u2 + jj;
                    mma16816(O[j], aPh[kkk], bh[2*jj], bh[2*jj+1]);
                    mma16816(O[j], aPl[kkk], bh[2*jj], bh[2*jj+1]);
                    mma16816(O[j], aPh[kkk], bl[2*jj], bl[2*jj+1]);
                }
            }
        }
        __syncthreads();   // stage st fully consumed before TMA refills it
    }

    lac0 += __shfl_xor_sync(0xffffffffu, lac0, 1);
    lac0 += __shfl_xor_sync(0xffffffffu, lac0, 2);
    lac1 += __shfl_xor_sync(0xffffffffu, lac1, 1);
    lac1 += __shfl_xor_sync(0xffffffffu, lac1, 2);
    float li0 = 1.0f / lac0, li1 = 1.0f / lac1;

    size_t rowA = base + (size_t)(q0 + 16*w + g) * DM;
    size_t rowB = base + (size_t)(q0 + 16*w + g + 8) * DM;
    #pragma unroll
    for (int j = 0; j < 8; j++) {
        int col = 8*j + 2*cq;
        unsigned uh, ul;
        split2(O[j][0] * li0, O[j][1] * li0, uh, ul);
        *(unsigned*)&Chi[rowA + col] = uh;
        *(unsigned*)&Clo[rowA + col] = ul;
        split2(O[j][2] * li1, O[j][3] * li1, uh, ul);
        *(unsigned*)&Chi[rowB + col] = uh;
        *(unsigned*)&Clo[rowB + col] = ul;
    }
}

// ---------------------------------------------------------------------------
typedef CUresult (*EncodeFn)(CUtensorMap*, CUtensorMapDataType, cuuint32_t, void*,
    const cuuint64_t*, const cuuint64_t*, const cuuint32_t*, const cuuint32_t*,
    CUtensorMapInterleave, CUtensorMapSwizzle, CUtensorMapL2promotion, CUtensorMapFloatOOBfill);

static void mk_map(CUtensorMap* m, void* p, unsigned long long inner, unsigned long long outer,
                   unsigned bx, unsigned by) {
    static EncodeFn fn = nullptr;
    if (!fn) {
        cudaDriverEntryPointQueryResult qr;
        cudaGetDriverEntryPointByVersion("cuTensorMapEncodeTiled", (void**)&fn, 12000,
                                         cudaEnableDefault, &qr);
    }
    cuuint64_t d[2] = {inner, outer}, s[1] = {inner * 2};
    cuuint32_t b[2] = {bx, by}, e[2] = {1, 1};
    fn(m, CU_TENSOR_MAP_DATA_TYPE_BFLOAT16, 2, p, d, s, b, e,
       CU_TENSOR_MAP_INTERLEAVE_NONE, CU_TENSOR_MAP_SWIZZLE_128B,
       CU_TENSOR_MAP_L2_PROMOTION_L2_128B, CU_TENSOR_MAP_FLOAT_OOB_FILL_NONE);
}

extern "C" void kernel_launch(void* const* d_in, const int* in_sizes, int n_in,
                              void* d_out, int out_size) {
    const float* hidden = (const float*)d_in[0];
    const float* lnw    = (const float*)d_in[1];
    const float* wq     = (const float*)d_in[2];
    const float* wk     = (const float*)d_in[3];
    const float* wv     = (const float*)d_in[4];
    const float* wo     = (const float*)d_in[5];
    const float* table  = (const float*)d_in[6];
    float* out = (float*)d_out;

    float *pbias2;
    __nv_bfloat16 *pahi, *palo, *pwhi, *pwlo, *pqh, *pql;
    cudaGetSymbolAddress((void**)&pbias2, g_bias2);
    cudaGetSymbolAddress((void**)&pahi,   g_ahi);
    cudaGetSymbolAddress((void**)&palo,   g_alo);
    cudaGetSymbolAddress((void**)&pwhi,   g_whi);
    cudaGetSymbolAddress((void**)&pwlo,   g_wlo);
    cudaGetSymbolAddress((void**)&pqh,    g_qkvh);
    cudaGetSymbolAddress((void**)&pql,    g_qkvl);

    CUtensorMap mAh, mAl, mWh, mWl, mQh, mQl;
    mk_map(&mAh, pahi, DM, ROWS,   64, 128);
    mk_map(&mAl, palo, DM, ROWS,   64, 128);
    mk_map(&mWh, pwhi, DM, 4*DM,   64, 64);
    mk_map(&mWl, pwlo, DM, 4*DM,   64, 64);
    mk_map(&mQh, pqh,  DM, 3*ROWS, 64, 64);
    mk_map(&mQl, pql,  DM, 3*ROWS, 64, 64);

    cudaFuncSetAttribute(attn_mma_kernel, cudaFuncAttributeMaxDynamicSharedMemorySize, ATT_DSM);
    cudaFuncSetAttribute(mma_gemm_kernel, cudaFuncAttributeMaxDynamicSharedMemorySize, G_DSM);

    bool full = out_size >= (HID_ELEMS + PB_ELEMS + 8);
    float* out_pb     = out + HID_ELEMS;
    float* out_remain = out + HID_ELEMS + PB_ELEMS;

    bias_fill_kernel<<<128, 256>>>(table, full ? out_remain : nullptr);
    if (full) pb_write_kernel<<<dim3(SEQ, NH), 256>>>(out_pb);

    split_w_kernel<<<4*WELEMS/256, 256>>>(wq, wk, wv, wo);
    split_a_kernel<<<ROWS, 128>>>(hidden, lnw);

    // QKV projections -> bf16 hi/lo planes (Q scaled by log2e)
    mma_gemm_kernel<<<dim3(DM/64, ROWS/128, 3), 256, G_DSM>>>(
        mAh, mAl, mWh, mWl, 0, nullptr, pqh, pql, (long long)HID_ELEMS, nullptr, 1);

    attn_mma_kernel<<<dim3(SEQ/128, NH, NBATCH), 256, ATT_DSM>>>(
        mQh, mQl, pqh, pql, pahi, palo, pbias2);

    // output projection + residual (fp32 out)
    mma_gemm_kernel<<<dim3(DM/64, ROWS/128, 1), 256, G_DSM>>>(
        mAh, mAl, mWh, mWl, 3, out, nullptr, nullptr, 0, hidden, 0);
}

// round 13
// speedup vs baseline: 1.0890x; 1.0251x over previous
#include <cuda_runtime.h>
#include <cuda.h>
#include <cuda_bf16.h>

#define NBATCH 8
#define SEQ 2048
#define DM 512
#define NH 8
#define DKV 64
#define ROWS (NBATCH*SEQ)
#define HID_ELEMS (ROWS*DM)
#define PB_ELEMS (NH*SEQ*SEQ)
#define WELEMS (DM*DM)
#define LOG2E 1.4426950408889634f

__device__ float g_bias[NH*4096];
__device__ float g_bias2[NH*4096];
__device__ __nv_bfloat16 g_ahi[HID_ELEMS];
__device__ __nv_bfloat16 g_alo[HID_ELEMS];
__device__ __nv_bfloat16 g_whi[4*WELEMS];    // [z][k][n]
__device__ __nv_bfloat16 g_wlo[4*WELEMS];
__device__ __nv_bfloat16 g_qkvh[3*HID_ELEMS];
__device__ __nv_bfloat16 g_qkvl[3*HID_ELEMS];

// ---------------- helpers ----------------
__device__ __forceinline__ unsigned smem_u32(const void* p) {
    unsigned a;
    asm("{ .reg .u64 t; cvta.to.shared.u64 t, %1; cvt.u32.u64 %0, t; }" : "=r"(a) : "l"(p));
    return a;
}
__device__ __forceinline__ unsigned sw128(unsigned x) { return x ^ ((x >> 3) & 0x70u); }
__device__ __forceinline__ void ldsm4(unsigned* r, unsigned addr) {
    asm volatile("ldmatrix.sync.aligned.m8n8.x4.shared.b16 {%0,%1,%2,%3}, [%4];"
        : "=r"(r[0]), "=r"(r[1]), "=r"(r[2]), "=r"(r[3]) : "r"(addr));
}
__device__ __forceinline__ void ldsm4t(unsigned* r, unsigned addr) {
    asm volatile("ldmatrix.sync.aligned.m8n8.x4.trans.shared.b16 {%0,%1,%2,%3}, [%4];"
        : "=r"(r[0]), "=r"(r[1]), "=r"(r[2]), "=r"(r[3]) : "r"(addr));
}
__device__ __forceinline__ void mma16816(float* c, const unsigned* a, unsigned b0, unsigned b1) {
    asm volatile("mma.sync.aligned.m16n8k16.row.col.f32.bf16.bf16.f32 "
        "{%0,%1,%2,%3}, {%4,%5,%6,%7}, {%8,%9}, {%0,%1,%2,%3};"
        : "+f"(c[0]), "+f"(c[1]), "+f"(c[2]), "+f"(c[3])
        : "r"(a[0]), "r"(a[1]), "r"(a[2]), "r"(a[3]), "r"(b0), "r"(b1));
}
__device__ __forceinline__ void tma2(unsigned dst, const CUtensorMap* m, int x, int y, unsigned mbar) {
    asm volatile("cp.async.bulk.tensor.2d.shared::cta.global.tile.mbarrier::complete_tx::bytes "
        "[%0], [%1, {%2, %3}], [%4];" :: "r"(dst), "l"(m), "r"(x), "r"(y), "r"(mbar) : "memory");
}
#define MBAR_INIT(a,c)   asm volatile("mbarrier.init.shared.b64 [%0], %1;" :: "r"((unsigned)(a)), "r"((unsigned)(c)) : "memory")
#define MBAR_EXPECT(a,b) asm volatile("mbarrier.arrive.expect_tx.shared.b64 _, [%0], %1;" :: "r"((unsigned)(a)), "r"((unsigned)(b)) : "memory")
__device__ __forceinline__ void mbar_wait(unsigned a, unsigned p) {
    asm volatile("{\n\t.reg .pred P;\n\tWL%=:\n\t"
        "mbarrier.try_wait.parity.acquire.cta.shared::cta.b64 P, [%0], %1, 0x989680;\n\t"
        "@P bra.uni WD%=;\n\tbra.uni WL%=;\n\tWD%=:\n\t}" :: "r"(a), "r"(p) : "memory");
}
__device__ __forceinline__ unsigned pack_bf16x2(float a, float b) {
    unsigned sa = __bfloat16_as_ushort(__float2bfloat16(a));
    unsigned sb = __bfloat16_as_ushort(__float2bfloat16(b));
    return sa | (sb << 16);
}
__device__ __forceinline__ void split2(float a, float b, unsigned& uh, unsigned& ul) {
    __nv_bfloat16 ha = __float2bfloat16(a), hb = __float2bfloat16(b);
    uh = (unsigned)__bfloat16_as_ushort(ha) | ((unsigned)__bfloat16_as_ushort(hb) << 16);
    ul = pack_bf16x2(a - __bfloat162float(ha), b - __bfloat162float(hb));
}
__device__ __forceinline__ float exp2_poly(float y) {
    float t = y + 12582912.0f;
    int k = __float_as_int(t);
    float f = y - (t - 12582912.0f);
    float p = 1.3333558146e-3f;
    p = fmaf(p, f, 9.6181291076e-3f);
    p = fmaf(p, f, 5.5504108664e-2f);
    p = fmaf(p, f, 2.4022650696e-1f);
    p = fmaf(p, f, 6.9314718056e-1f);
    p = fmaf(p, f, 1.0f);
    return __int_as_float(__float_as_int(p) + (k << 23));
}

// ---------------- small kernels ----------------
__global__ void bias_fill_kernel(const float* __restrict__ table, float* __restrict__ out_remain) {
    int idx = blockIdx.x * blockDim.x + threadIdx.x;
    if (idx < NH * 4096) {
        int h = idx >> 12;
        int rel = (idx & 4095) - 2047;
        int a = rel < 0 ? -rel : rel;
        int b;
        if (a < 8) b = a;
        else {
            int e = 28 - __clz(a);
            long long aa = (long long)a * (long long)a;
            b = 8 + 2*e + ((aa >= (1LL << (2*e + 7))) ? 1 : 0);
            if (b > 15) b = 15;
        }
        int bucket = (rel > 0 ? 16 : 0) + b;
        float val = table[bucket * NH + h];
        g_bias[idx] = val;
        g_bias2[idx] = val * LOG2E;
    }
    if (out_remain != nullptr && idx < 8) out_remain[idx] = (float)idx;
}

__global__ void pb_write_kernel(float* __restrict__ out_pb) {
    int q = blockIdx.x, h = blockIdx.y;
    const float* brow = g_bias + h * 4096 + (2047 - q);
    float* dst = out_pb + ((size_t)(h * SEQ + q)) * SEQ;
    int t = threadIdx.x;
    #pragma unroll
    for (int it = 0; it < 2; it++) {
        int k4 = (t + it * 256) * 4;
        *(float4*)&dst[k4] = make_float4(brow[k4], brow[k4+1], brow[k4+2], brow[k4+3]);
    }
}

__global__ void split_w_kernel(const float* __restrict__ wq, const float* __restrict__ wk,
                               const float* __restrict__ wv, const float* __restrict__ wo) {
    int idx = blockIdx.x * 256 + threadIdx.x;
    const float* src = (idx < WELEMS) ? wq : (idx < 2*WELEMS) ? wk : (idx < 3*WELEMS) ? wv : wo;
    float x = src[idx & (WELEMS - 1)];
    __nv_bfloat16 h = __float2bfloat16(x);
    g_whi[idx] = h;
    g_wlo[idx] = __float2bfloat16(x - __bfloat162float(h));
}

__global__ void split_a_kernel(const float* __restrict__ hidden, const float* __restrict__ lnw) {
    int m = blockIdx.x, t = threadIdx.x;
    float4 v = *(const float4*)&hidden[(size_t)m * DM + t * 4];
    float s = v.x*v.x + v.y*v.y + v.z*v.z + v.w*v.w;
    #pragma unroll
    for (int off = 16; off > 0; off >>= 1) s += __shfl_xor_sync(0xffffffffu, s, off);
    __shared__ float ws[4];
    if ((t & 31) == 0) ws[t >> 5] = s;
    __syncthreads();
    float rms = rsqrtf((ws[0]+ws[1]+ws[2]+ws[3]) * (1.0f/(float)DM) + 1e-6f);
    float4 l = *(const float4*)&lnw[t * 4];
    float a0 = v.x*l.x*rms, a1 = v.y*l.y*rms, a2 = v.z*l.z*rms, a3 = v.w*l.w*rms;
    unsigned uh0, ul0, uh1, ul1;
    split2(a0, a1, uh0, ul0);
    split2(a2, a3, uh1, ul1);
    *(uint2*)&g_ahi[(size_t)m * DM + t * 4] = make_uint2(uh0, uh1);
    *(uint2*)&g_alo[(size_t)m * DM + t * 4] = make_uint2(ul0, ul1);
}

// ---------------------------------------------------------------------------
// bf16x3 mma.sync GEMM, TMA-fed 2-stage pipeline (unchanged from round 12).
// ---------------------------------------------------------------------------
#define G_STG 49152u
#define G_DSM (2*49152 + 1024)

__global__ __launch_bounds__(256) void mma_gemm_kernel(
    const __grid_constant__ CUtensorMap mAh, const __grid_constant__ CUtensorMap mAl,
    const __grid_constant__ CUtensorMap mWh, const __grid_constant__ CUtensorMap mWl,
    int wbase, float* __restrict__ DstF,
    __nv_bfloat16* __restrict__ DstH, __nv_bfloat16* __restrict__ DstL,
    long long dzs, const float* __restrict__ resid, int qkv_mode)
{
    extern __shared__ char gsm[];
    __shared__ __align__(8) unsigned long long mb[2];
    unsigned sb = (smem_u32(gsm) + 1023u) & ~1023u;
    int t = threadIdx.x, w = t >> 5, lane = t & 31;
    int n0 = blockIdx.x * 64, m0 = blockIdx.y * 128, z = blockIdx.z;
    int wm = (w >> 1) * 32, wn = (w & 1) * 32;
    int wr = (wbase + z) * DM;

    float c[2][4][4];
    #pragma unroll
    for (int i = 0; i < 2; i++)
        #pragma unroll
        for (int j = 0; j < 4; j++)
            #pragma unroll
            for (int k = 0; k < 4; k++) c[i][j][k] = 0.0f;

    int lrowA = lane & 15, lkA = (lane >> 4) * 8;
    int lkB = (lane & 7) + ((lane & 8) ? 8 : 0);
    int lnB = (lane & 16) ? 8 : 0;

    if (t == 0) { MBAR_INIT(smem_u32(&mb[0]), 1); MBAR_INIT(smem_u32(&mb[1]), 1); }
    __syncthreads();
    if (t == 0) {
        unsigned m0b = smem_u32(&mb[0]);
        MBAR_EXPECT(m0b, G_STG);
        tma2(sb,         &mAh, 0, m0, m0b);
        tma2(sb + 16384, &mAl, 0, m0, m0b);
        tma2(sb + 32768, &mWh, n0, wr, m0b);
        tma2(sb + 40960, &mWl, n0, wr, m0b);
    }
    int ph[2] = {0, 0};
    for (int s = 0; s < 8; s++) {
        int b = s & 1;
        unsigned st = sb + (unsigned)b * G_STG;
        if (s + 1 < 8 && t == 0) {
            unsigned sn = sb + (unsigned)(b ^ 1) * G_STG;
            unsigned mbn = smem_u32(&mb[b ^ 1]);
            MBAR_EXPECT(mbn, G_STG);
            tma2(sn,         &mAh, (s+1)*64, m0, mbn);
            tma2(sn + 16384, &mAl, (s+1)*64, m0, mbn);
            tma2(sn + 32768, &mWh, n0, wr + (s+1)*64, mbn);
            tma2(sn + 40960, &mWl, n0, wr + (s+1)*64, mbn);
        }
        mbar_wait(smem_u32(&mb[b]), ph[b]); ph[b] ^= 1;

        #pragma unroll
        for (int kk = 0; kk < 64; kk += 16) {
            unsigned ah[2][4], al[2][4], bh[2][4], bl[2][4];
            #pragma unroll
            for (int mf = 0; mf < 2; mf++) {
                unsigned sa = sw128((unsigned)((wm + mf*16 + lrowA)*128 + (kk + lkA)*2));
                ldsm4(ah[mf], st + sa);
                ldsm4(al[mf], st + 16384 + sa);
            }
            #pragma unroll
            for (int nh = 0; nh < 2; nh++) {
                unsigned sa = sw128((unsigned)((kk + lkB)*128 + (wn + nh*16 + lnB)*2));
                ldsm4t(bh[nh], st + 32768 + sa);
                ldsm4t(bl[nh], st + 40960 + sa);
            }
            #pragma unroll
            for (int mf = 0; mf < 2; mf++)
                #pragma unroll
                for (int nf = 0; nf < 4; nf++) {
                    unsigned b0h = bh[nf >> 1][(nf & 1)*2], b1h = bh[nf >> 1][(nf & 1)*2 + 1];
                    unsigned b0l = bl[nf >> 1][(nf & 1)*2], b1l = bl[nf >> 1][(nf & 1)*2 + 1];
                    mma16816(c[mf][nf], ah[mf], b0h, b1h);
                    mma16816(c[mf][nf], ah[mf], b0l, b1l);
                    mma16816(c[mf][nf], al[mf], b0h, b1h);
                }
        }
        __syncthreads();
    }

    int g = lane >> 2, tc = (lane & 3) * 2;
    float sc = (qkv_mode && z == 0) ? LOG2E : 1.0f;
    #pragma unroll
    for (int mf = 0; mf < 2; mf++)
        #pragma unroll
        for (int nf = 0; nf < 4; nf++) {
            int row = m0 + wm + mf*16 + g;
            int col = n0 + wn + nf*8 + tc;
            float v0 = c[mf][nf][0]*sc, v1 = c[mf][nf][1]*sc;
            float v2 = c[mf][nf][2]*sc, v3 = c[mf][nf][3]*sc;
            if (DstF) {
                if (resid) {
                    float2 r0 = *(const float2*)&resid[(size_t)row*DM + col];
                    float2 r1 = *(const float2*)&resid[(size_t)(row+8)*DM + col];
                    v0 += r0.x; v1 += r0.y; v2 += r1.x; v3 += r1.y;
                }
                *(float2*)&DstF[(size_t)row*DM + col] = make_float2(v0, v1);
                *(float2*)&DstF[(size_t)(row+8)*DM + col] = make_float2(v2, v3);
            } else {
                size_t zo = (size_t)z * dzs;
                unsigned uh, ul;
                split2(v0, v1, uh, ul);
                *(unsigned*)&DstH[zo + (size_t)row*DM + col] = uh;
                *(unsigned*)&DstL[zo + (size_t)row*DM + col] = ul;
                split2(v2, v3, uh, ul);
                *(unsigned*)&DstH[zo + (size_t)(row+8)*DM + col] = uh;
                *(unsigned*)&DstL[zo + (size_t)(row+8)*DM + col] = ul;
            }
        }
}

// ---------------------------------------------------------------------------
// Flash attention, TMA-fed. Exp2/split now interleaved per key-chunk with the
// PV MMAs: FMA-pipe exp work issues while previous chunk's HMMAs drain the
// tensor pipe (single-warp dual-pipe overlap). Arithmetic order identical.
// ---------------------------------------------------------------------------
#define ATT_STG 32768u
#define ATT_DSM (65536 + 1536 + 1024)

__global__ __launch_bounds__(256) void attn_mma_kernel(
    const __grid_constant__ CUtensorMap mH, const __grid_constant__ CUtensorMap mL,
    const __nv_bfloat16* __restrict__ Qh, const __nv_bfloat16* __restrict__ Ql,
    __nv_bfloat16* __restrict__ Chi, __nv_bfloat16* __restrict__ Clo,
    const float* __restrict__ Bias2)
{
    extern __shared__ char dyns[];
    __shared__ __align__(8) unsigned long long mb[2];
    unsigned sb = (smem_u32(dyns) + 1023u) & ~1023u;
    char* ab = dyns + (sb - smem_u32(dyns));
    float* sB = (float*)(ab + 65536);

    int t = threadIdx.x, w = t >> 5, lane = t & 31;
    int g = lane >> 2, cq = lane & 3;
    int q0 = blockIdx.x * 128, h = blockIdx.y, n = blockIdx.z;
    size_t base = ((size_t)n * SEQ) * DM + h * DKV;
    const float* brow = Bias2 + h * 4096;

    if (t == 0) { MBAR_INIT(smem_u32(&mb[0]), 1); MBAR_INIT(smem_u32(&mb[1]), 1); }

    // Q prologue: stage into scratch (stage area; consumed before prefetch 0)
    {
        __nv_bfloat16* Qs_h = (__nv_bfloat16*)ab;
        __nv_bfloat16* Qs_l = (__nv_bfloat16*)(ab + 18432);
        #pragma unroll
        for (int it = 0; it < 4; it++) {
            int slot = t + 256*it;
            int row = slot >> 3, c8 = (slot & 7) * 8;
            *(uint4*)&Qs_h[row*72 + c8] = *(const uint4*)&Qh[base + (size_t)(q0+row)*DM + c8];
            *(uint4*)&Qs_l[row*72 + c8] = *(const uint4*)&Ql[base + (size_t)(q0+row)*DM + c8];
        }
    }
    __syncthreads();
    unsigned qfh[4][4], qfl[4][4];
    #pragma unroll
    for (int kk = 0; kk < 4; kk++) {
        unsigned addr = (unsigned)((16*w + (lane & 15))*72 + 16*kk + ((lane >> 4)*8)) * 2;
        ldsm4(qfh[kk], sb + addr);
        ldsm4(qfl[kk], sb + 18432 + addr);
    }
    __syncthreads();   // Q reads done; stage area free for TMA

    float O[8][4];
    #pragma unroll
    for (int j = 0; j < 8; j++)
        #pragma unroll
        for (int e = 0; e < 4; e++) O[j][e] = 0.0f;
    float lac0 = 0.0f, lac1 = 0.0f;

    int yK = ROWS + n*SEQ;   // K plane row base; V = +ROWS
    if (t == 0) {
        unsigned m0b = smem_u32(&mb[0]);
        MBAR_EXPECT(m0b, ATT_STG);
        tma2(sb,         &mH, h*64, yK, m0b);
        tma2(sb + 8192,  &mL, h*64, yK, m0b);
        tma2(sb + 16384, &mH, h*64, yK + ROWS, m0b);
        tma2(sb + 24576, &mL, h*64, yK + ROWS, m0b);
    }
    if (t < 192) sB[t] = brow[0 - q0 + 1920 + t];
    __syncthreads();   // sB stage-0 visible before first read

    int ph[2] = {0, 0};
    const int NB = SEQ / 64;
    int r0 = 16*w + g;
    for (int kb = 0; kb < NB; kb++) {
        int st = kb & 1;
        unsigned stc = sb + (unsigned)st * ATT_STG;
        if (kb + 1 < NB) {
            if (t == 0) {
                unsigned stn = sb + (unsigned)(st ^ 1) * ATT_STG;
                unsigned mbn = smem_u32(&mb[st ^ 1]);
                MBAR_EXPECT(mbn, ATT_STG);
                int y = yK + (kb+1)*64;
                tma2(stn,         &mH, h*64, y, mbn);
                tma2(stn + 8192,  &mL, h*64, y, mbn);
                tma2(stn + 16384, &mH, h*64, y + ROWS, mbn);
                tma2(stn + 24576, &mL, h*64, y + ROWS, mbn);
            }
            if (t < 192) sB[(st^1)*192 + t] = brow[(kb+1)*64 - q0 + 1920 + t];
        }
        mbar_wait(smem_u32(&mb[st]), ph[st]); ph[st] ^= 1;
        const float* sBc = sB + st*192;

        // ---- S = Q K^T (bf16x3) ----
        float S[8][4];
        #pragma unroll
        for (int j = 0; j < 8; j++)
            #pragma unroll
            for (int e = 0; e < 4; e++) S[j][e] = 0.0f;

        #pragma unroll
        for (int kk = 0; kk < 4; kk++) {
            #pragma unroll
            for (int u = 0; u < 4; u++) {
                unsigned bh[4], bl[4];
                unsigned sa = sw128((unsigned)((16*u + (lane & 7) + ((lane & 16) ? 8 : 0))*128
                                               + 32*kk + ((lane & 8) ? 16 : 0)));
                ldsm4(bh, stc + sa);
                ldsm4(bl, stc + 8192 + sa);
                #pragma unroll
                for (int jj = 0; jj < 2; jj++) {
                    int j = 2*u + jj;
                    mma16816(S[j], qfh[kk], bh[2*jj], bh[2*jj+1]);
                    mma16816(S[j], qfl[kk], bh[2*jj], bh[2*jj+1]);
                    mma16816(S[j], qfh[kk], bl[2*jj], bl[2*jj+1]);
                }
            }
        }

        // ---- interleaved: per key-chunk kkk, exp2+split then PV MMAs.
        //      exp2 (FMA pipe) overlaps the previous chunk's HMMA drain. ----
        #pragma unroll
        for (int kkk = 0; kkk < 4; kkk++) {
            unsigned aPh4[4], aPl4[4];
            #pragma unroll
            for (int jj = 0; jj < 2; jj++) {
                int j = 2*kkk + jj;
                int col = 8*j + 2*cq;
                float p0 = exp2_poly(S[j][0] + sBc[col     - r0 + 127]);
                float p1 = exp2_poly(S[j][1] + sBc[col + 1 - r0 + 127]);
                float p2 = exp2_poly(S[j][2] + sBc[col     - r0 + 119]);
                float p3 = exp2_poly(S[j][3] + sBc[col + 1 - r0 + 119]);
                lac0 += p0 + p1;
                lac1 += p2 + p3;
                unsigned uh01, ul01, uh23, ul23;
                split2(p0, p1, uh01, ul01);
                split2(p2, p3, uh23, ul23);
                aPh4[jj*2    ] = uh01;
                aPh4[jj*2 + 1] = uh23;
                aPl4[jj*2    ] = ul01;
                aPl4[jj*2 + 1] = ul23;
            }
            #pragma unroll
            for (int u2 = 0; u2 < 4; u2++) {
                unsigned bh[4], bl[4];
                unsigned sa = sw128((unsigned)((16*kkk + (lane & 7) + ((lane & 8) ? 8 : 0))*128
                                               + 32*u2 + ((lane & 16) ? 16 : 0)));
                ldsm4t(bh, stc + 16384 + sa);
                ldsm4t(bl, stc + 24576 + sa);
                #pragma unroll
                for (int jj = 0; jj < 2; jj++) {
                    int j = 2*u2 + jj;
                    mma16816(O[j], aPh4, bh[2*jj], bh[2*jj+1]);
                    mma16816(O[j], aPl4, bh[2*jj], bh[2*jj+1]);
                    mma16816(O[j], aPh4, bl[2*jj], bl[2*jj+1]);
                }
            }
        }
        __syncthreads();   // stage st fully consumed before TMA refills it
    }

    lac0 += __shfl_xor_sync(0xffffffffu, lac0, 1);
    lac0 += __shfl_xor_sync(0xffffffffu, lac0, 2);
    lac1 += __shfl_xor_sync(0xffffffffu, lac1, 1);
    lac1 += __shfl_xor_sync(0xffffffffu, lac1, 2);
    float li0 = 1.0f / lac0, li1 = 1.0f / lac1;

    size_t rowA = base + (size_t)(q0 + 16*w + g) * DM;
    size_t rowB = base + (size_t)(q0 + 16*w + g + 8) * DM;
    #pragma unroll
    for (int j = 0; j < 8; j++) {
        int col = 8*j + 2*cq;
        unsigned uh, ul;
        split2(O[j][0] * li0, O[j][1] * li0, uh, ul);
        *(unsigned*)&Chi[rowA + col] = uh;
        *(unsigned*)&Clo[rowA + col] = ul;
        split2(O[j][2] * li1, O[j][3] * li1, uh, ul);
        *(unsigned*)&Chi[rowB + col] = uh;
        *(unsigned*)&Clo[rowB + col] = ul;
    }
}

// ---------------------------------------------------------------------------
typedef CUresult (*EncodeFn)(CUtensorMap*, CUtensorMapDataType, cuuint32_t, void*,
    const cuuint64_t*, const cuuint64_t*, const cuuint32_t*, const cuuint32_t*,
    CUtensorMapInterleave, CUtensorMapSwizzle, CUtensorMapL2promotion, CUtensorMapFloatOOBfill);

static void mk_map(CUtensorMap* m, void* p, unsigned long long inner, unsigned long long outer,
                   unsigned bx, unsigned by) {
    static EncodeFn fn = nullptr;
    if (!fn) {
        cudaDriverEntryPointQueryResult qr;
        cudaGetDriverEntryPointByVersion("cuTensorMapEncodeTiled", (void**)&fn, 12000,
                                         cudaEnableDefault, &qr);
    }
    cuuint64_t d[2] = {inner, outer}, s[1] = {inner * 2};
    cuuint32_t b[2] = {bx, by}, e[2] = {1, 1};
    fn(m, CU_TENSOR_MAP_DATA_TYPE_BFLOAT16, 2, p, d, s, b, e,
       CU_TENSOR_MAP_INTERLEAVE_NONE, CU_TENSOR_MAP_SWIZZLE_128B,
       CU_TENSOR_MAP_L2_PROMOTION_L2_128B, CU_TENSOR_MAP_FLOAT_OOB_FILL_NONE);
}

extern "C" void kernel_launch(void* const* d_in, const int* in_sizes, int n_in,
                              void* d_out, int out_size) {
    const float* hidden = (const float*)d_in[0];
    const float* lnw    = (const float*)d_in[1];
    const float* wq     = (const float*)d_in[2];
    const float* wk     = (const float*)d_in[3];
    const float* wv     = (const float*)d_in[4];
    const float* wo     = (const float*)d_in[5];
    const float* table  = (const float*)d_in[6];
    float* out = (float*)d_out;

    float *pbias2;
    __nv_bfloat16 *pahi, *palo, *pwhi, *pwlo, *pqh, *pql;
    cudaGetSymbolAddress((void**)&pbias2, g_bias2);
    cudaGetSymbolAddress((void**)&pahi,   g_ahi);
    cudaGetSymbolAddress((void**)&palo,   g_alo);
    cudaGetSymbolAddress((void**)&pwhi,   g_whi);
    cudaGetSymbolAddress((void**)&pwlo,   g_wlo);
    cudaGetSymbolAddress((void**)&pqh,    g_qkvh);
    cudaGetSymbolAddress((void**)&pql,    g_qkvl);

    CUtensorMap mAh, mAl, mWh, mWl, mQh, mQl;
    mk_map(&mAh, pahi, DM, ROWS,   64, 128);
    mk_map(&mAl, palo, DM, ROWS,   64, 128);
    mk_map(&mWh, pwhi, DM, 4*DM,   64, 64);
    mk_map(&mWl, pwlo, DM, 4*DM,   64, 64);
    mk_map(&mQh, pqh,  DM, 3*ROWS, 64, 64);
    mk_map(&mQl, pql,  DM, 3*ROWS, 64, 64);

    cudaFuncSetAttribute(attn_mma_kernel, cudaFuncAttributeMaxDynamicSharedMemorySize, ATT_DSM);
    cudaFuncSetAttribute(mma_gemm_kernel, cudaFuncAttributeMaxDynamicSharedMemorySize, G_DSM);

    bool full = out_size >= (HID_ELEMS + PB_ELEMS + 8);
    float* out_pb     = out + HID_ELEMS;
    float* out_remain = out + HID_ELEMS + PB_ELEMS;

    bias_fill_kernel<<<128, 256>>>(table, full ? out_remain : nullptr);
    if (full) pb_write_kernel<<<dim3(SEQ, NH), 256>>>(out_pb);

    split_w_kernel<<<4*WELEMS/256, 256>>>(wq, wk, wv, wo);
    split_a_kernel<<<ROWS, 128>>>(hidden, lnw);

    mma_gemm_kernel<<<dim3(DM/64, ROWS/128, 3), 256, G_DSM>>>(
        mAh, mAl, mWh, mWl, 0, nullptr, pqh, pql, (long long)HID_ELEMS, nullptr, 1);

    attn_mma_kernel<<<dim3(SEQ/128, NH, NBATCH), 256, ATT_DSM>>>(
        mQh, mQl, pqh, pql, pahi, palo, pbias2);

    mma_gemm_kernel<<<dim3(DM/64, ROWS/128, 1), 256, G_DSM>>>(
        mAh, mAl, mWh, mWl, 3, out, nullptr, nullptr, 0, hidden, 0);
}